// round 3
// baseline (speedup 1.0000x reference)
#include <cuda_runtime.h>
#include <cuda_bf16.h>
#include <cstdint>

// Persistent-kernel Sinkhorn (exp-domain), fp32 throughout.
// E = exp(padded_scores) resident in SMEM as fp32 row slabs, distributed over
// 148 CTAs (1/SM). Phase A (row sums) local; phase B (col sums) via per-CTA
// fp32 partials in global + cross-CTA gather. All cross-SM reads use __ldcg.
// Masks: runtime dtype detection (bool may arrive as int32/float32 from harness).

#define NCTA   148
#define CPB    37            // CTAs per batch (148 = 4*37)
#define RPC    28            // rows per CTA (37*28 = 1036 >= 1025)
#define SF     1028          // slab row stride in floats
#define MDIM   1024
#define MP     1025
#define NITER  100
#define TPB    256

#define SLAB_BYTES (RPC * SF * 4)
#define SMEM_BYTES (SLAB_BYTES + SF * 4 + 64 * 4)

__device__ float        g_v[4 * MP];
__device__ float        g_part[NCTA][SF];
__device__ unsigned int g_count = 0;   // monotonic arrivals
__device__ unsigned int g_gen   = 0;   // monotonic generation

__device__ __forceinline__ void grid_barrier(unsigned int* bar_idx, unsigned int gen0)
{
    __syncthreads();
    unsigned int target = gen0 + (++(*bar_idx));
    if (threadIdx.x == 0) {
        __threadfence();
        unsigned int old = atomicAdd(&g_count, 1u);
        if ((old % NCTA) == (NCTA - 1)) {
            atomicAdd(&g_gen, 1u);                       // release
        } else {
            while ((int)(*((volatile unsigned int*)&g_gen) - target) < 0) { }
        }
        __threadfence();
    }
    __syncthreads();
}

__global__ void __launch_bounds__(TPB, 1)
sinkhorn_kernel(const float* __restrict__ scores,
                const void* __restrict__ rmaskp,
                const void* __restrict__ cmaskp,
                const float* __restrict__ alphap,
                float* __restrict__ out)
{
    extern __shared__ unsigned char smem[];
    float* rowSlab = (float*)smem;                       // RPC x SF fp32
    float* vecbuf  = (float*)(smem + SLAB_BYTES);        // SF floats
    float* w_buf   = (float*)(smem + SLAB_BYTES + SF * 4);        // 32
    float* u_buf   = w_buf + 32;                                   // 32

    __shared__ unsigned int s_gen0;
    __shared__ int s_cnt[2];
    __shared__ int s_mode;            // 0 = byte bools, 1 = 4-byte elems
    __shared__ float s_alpha;

    const int tid  = threadIdx.x;
    const int lane = tid & 31;
    const int warp = tid >> 5;
    const int b    = blockIdx.x / CPB;
    const int rblk = blockIdx.x % CPB;
    const int row0 = rblk * RPC;
    const int rows = min(RPC, MP - row0);   // 28 or 17
    const int col0 = row0;
    const int cols = rows;

    if (tid == 0) {
        s_gen0 = *((volatile unsigned int*)&g_gen);
        s_cnt[0] = 0; s_cnt[1] = 0;
        s_alpha = alphap[0];
        // ---- detect mask element width ----
        // byte-packed bools (all-true) -> words look like 0x01010101
        // int32 bools   -> words are 0 / 1
        // float32 bools -> words are 0 / 0x3F800000
        const unsigned int* rw = (const unsigned int*)rmaskp;
        int mode = 1;
        #pragma unroll
        for (int k = 0; k < 8; k++)
            if (rw[k] == 0x01010101u) mode = 0;
        s_mode = mode;
    }
    __syncthreads();

    // ---- mask counts (num_valid_row / num_valid_col for this batch) ----
    {
        int pr = 0, pc = 0;
        if (s_mode == 1) {
            const unsigned int* rm = (const unsigned int*)rmaskp + b * MDIM;
            const unsigned int* cm = (const unsigned int*)cmaskp + b * MDIM;
            #pragma unroll
            for (int k = 0; k < 4; k++) {
                int i = tid * 4 + k;
                pr += (rm[i] != 0u);
                pc += (cm[i] != 0u);
            }
        } else {
            const unsigned char* rm = (const unsigned char*)rmaskp + b * MDIM;
            const unsigned char* cm = (const unsigned char*)cmaskp + b * MDIM;
            #pragma unroll
            for (int k = 0; k < 4; k++) {
                int i = tid * 4 + k;
                pr += (rm[i] != 0);
                pc += (cm[i] != 0);
            }
        }
        for (int o = 16; o; o >>= 1) {
            pr += __shfl_xor_sync(~0u, pr, o);
            pc += __shfl_xor_sync(~0u, pc, o);
        }
        if (lane == 0) { atomicAdd(&s_cnt[0], pr); atomicAdd(&s_cnt[1], pc); }
    }
    __syncthreads();

    const float R      = (float)s_cnt[0];
    const float C      = (float)s_cnt[1];
    const float norm   = -logf(R + C);
    const float logmuD = logf(C) + norm;
    const float lognuD = logf(R) + norm;
    const float alpha  = s_alpha;
    const float ea     = expf(alpha);

    // ---- zero v for our columns ----
    for (int c = tid; c < cols; c += TPB) g_v[b * MP + col0 + c] = 0.f;

    // ---- build fp32 row slab E[row, :] ----
    const float* sb = scores + (size_t)b * MDIM * MDIM;
    for (int rr = 0; rr < rows; rr++) {
        const int row = row0 + rr;
        float* dst = rowSlab + rr * SF;
        if (row < MDIM) {
            const float* sp = sb + (size_t)row * MDIM;
            for (int j = tid; j < SF; j += TPB)
                dst[j] = (j < MDIM) ? expf(sp[j]) : ((j == MDIM) ? ea : 0.f);
        } else {
            for (int j = tid; j < SF; j += TPB)
                dst[j] = (j < MP) ? ea : 0.f;
        }
    }

    unsigned int bar = 0;
    grid_barrier(&bar, s_gen0);   // all g_v zeroed

    const float4* slab4 = (const float4*)rowSlab;        // 257 float4 per row

    for (int it = 0; it < NITER; it++) {
        // ========== phase A: u_i = log_mu_i - log sum_j E_ij exp(v_j) (local rows) ====
        for (int j = tid; j < SF; j += TPB)
            vecbuf[j] = (j < MP) ? expf(__ldcg(&g_v[b * MP + j])) : 0.f;
        __syncthreads();

        float4 wreg[8];
        {
            const float4* v4 = (const float4*)vecbuf;
            #pragma unroll
            for (int i = 0; i < 8; i++) wreg[i] = v4[lane + 32 * i];
        }
        const float wtail = vecbuf[1024];

        for (int rr = warp; rr < rows; rr += 8) {
            const float4* rp = slab4 + rr * 257;
            float a0 = 0.f, a1 = 0.f, a2 = 0.f, a3 = 0.f;
            #pragma unroll
            for (int i = 0; i < 8; i++) {
                const float4 p = rp[lane + 32 * i];
                a0 += p.x * wreg[i].x;
                a1 += p.y * wreg[i].y;
                a2 += p.z * wreg[i].z;
                a3 += p.w * wreg[i].w;
            }
            float acc = (a0 + a1) + (a2 + a3);
            if (lane == 0) acc += rowSlab[rr * SF + 1024] * wtail;
            for (int o = 16; o; o >>= 1) acc += __shfl_xor_sync(~0u, acc, o);
            if (lane == 0) {
                const int row = row0 + rr;
                const float lm = (row == MDIM) ? logmuD : norm;
                const float u  = lm - logf(acc);
                u_buf[rr] = u;
                w_buf[rr] = expf(u);
            }
        }
        __syncthreads();   // w_buf ready (local)

        // ========== phase B: partial col sums over our rows ============================
        float4 acc4 = make_float4(0.f, 0.f, 0.f, 0.f);
        float  accT = 0.f;
        for (int rr = 0; rr < rows; rr++) {
            const float w  = w_buf[rr];
            const float4 e = slab4[rr * 257 + tid];
            acc4.x += e.x * w; acc4.y += e.y * w;
            acc4.z += e.z * w; acc4.w += e.w * w;
            if (tid == 0) accT += rowSlab[rr * SF + 1024] * w;
        }
        ((float4*)g_part[blockIdx.x])[tid] = acc4;       // cols 0..1023
        if (tid == 0) g_part[blockIdx.x][1024] = accT;   // col 1024

        grid_barrier(&bar, s_gen0);                      // all partials visible

        // ========== gather: v_j for our cols ==========================================
        {
            const int c = tid >> 3;
            const int k = tid & 7;
            float s = 0.f;
            if (c < cols) {
                const int col = col0 + c;
                #pragma unroll
                for (int pp = 0; pp < 5; pp++) {
                    const int p = k + 8 * pp;
                    if (p < CPB) s += __ldcg(&g_part[b * CPB + p][col]);
                }
            }
            s += __shfl_xor_sync(~0u, s, 1);
            s += __shfl_xor_sync(~0u, s, 2);
            s += __shfl_xor_sync(~0u, s, 4);
            if (c < cols && k == 0) {
                const int col = col0 + c;
                const float ln = (col == MDIM) ? lognuD : norm;
                g_v[b * MP + col] = ln - logf(s);
            }
        }

        grid_barrier(&bar, s_gen0);                      // all v visible
    }

    // ========== output: out = padded_scores + u_i + v_j - norm ========================
    for (int j = tid; j < MP; j += TPB) vecbuf[j] = __ldcg(&g_v[b * MP + j]);
    __syncthreads();

    float* ob = out + (size_t)b * MP * MP;
    for (int rr = 0; rr < rows; rr++) {
        const int row = row0 + rr;
        const float base = u_buf[rr] - norm;
        float* op = ob + (size_t)row * MP;
        if (row < MDIM) {
            const float* sp = sb + (size_t)row * MDIM;
            for (int j = tid; j < MP; j += TPB) {
                const float s = (j < MDIM) ? sp[j] : alpha;
                op[j] = s + base + vecbuf[j];
            }
        } else {
            for (int j = tid; j < MP; j += TPB)
                op[j] = alpha + base + vecbuf[j];
        }
    }
}

extern "C" void kernel_launch(void* const* d_in, const int* in_sizes, int n_in,
                              void* d_out, int out_size)
{
    const float* scores = (const float*)d_in[0];
    const void*  rmask  = d_in[1];
    const void*  cmask  = d_in[2];
    const float* alphap = (const float*)d_in[3];
    float*       out    = (float*)d_out;

    cudaFuncSetAttribute(sinkhorn_kernel,
                         cudaFuncAttributeMaxDynamicSharedMemorySize, SMEM_BYTES);
    sinkhorn_kernel<<<NCTA, TPB, SMEM_BYTES>>>(scores, rmask, cmask, alphap, out);
}

// round 4
// speedup vs baseline: 1.1561x; 1.1561x over previous
#include <cuda_runtime.h>
#include <cstdint>

// Persistent-kernel Sinkhorn, exp-domain ratio form (no exp/log in the loop).
// E = exp(padded_scores) resident in SMEM fp32 row slabs, 148 CTAs (1/SM).
// Per iteration: row sums local; col sums via atomicAdd(RED) into a rotating
// 3-slot global accumulator; ONE acq_rel grid barrier; each CTA then reads its
// batch's 4KB colsum vector and forms w_v locally. Logs only in the epilogue.

#define NCTA   148
#define CPB    37            // CTAs per batch (148 = 4*37)
#define RPC    28            // rows per CTA (37*28 = 1036 >= 1025)
#define SF     1028          // slab row stride in floats
#define MDIM   1024
#define MP     1025
#define NITER  100
#define TPB    256

#define SLAB_BYTES (RPC * SF * 4)
#define SMEM_BYTES (SLAB_BYTES + SF * 4 + 64 * 4)

__device__ float        g_acc[3][4][SF];   // rotating colsum accumulators
__device__ unsigned int g_count = 0;       // monotonic arrivals
__device__ unsigned int g_gen   = 0;       // monotonic generation

__device__ __forceinline__ void grid_barrier(unsigned int* bar_idx, unsigned int gen0)
{
    __syncthreads();
    unsigned int target = gen0 + (++(*bar_idx));
    if (threadIdx.x == 0) {
        unsigned int old;
        asm volatile("atom.acq_rel.gpu.add.u32 %0, [%1], %2;"
                     : "=r"(old) : "l"(&g_count), "r"(1u) : "memory");
        if (old % NCTA == NCTA - 1u) {
            asm volatile("red.release.gpu.add.u32 [%0], %1;"
                         :: "l"(&g_gen), "r"(1u) : "memory");
        } else {
            unsigned int g;
            do {
                asm volatile("ld.acquire.gpu.u32 %0, [%1];"
                             : "=r"(g) : "l"(&g_gen) : "memory");
            } while ((int)(g - target) < 0);
        }
    }
    __syncthreads();
}

__global__ void __launch_bounds__(TPB, 1)
sinkhorn_kernel(const float* __restrict__ scores,
                const void* __restrict__ rmaskp,
                const void* __restrict__ cmaskp,
                const float* __restrict__ alphap,
                float* __restrict__ out)
{
    extern __shared__ unsigned char smem[];
    float* rowSlab = (float*)smem;                       // RPC x SF fp32
    float* vecbuf  = (float*)(smem + SLAB_BYTES);        // SF floats: w_v (then v)
    float* w_buf   = (float*)(smem + SLAB_BYTES + SF * 4);  // 32: w_u per local row
    float* r_buf   = w_buf + 32;                             // 32: last rowsum

    __shared__ unsigned int s_gen0;
    __shared__ int s_cnt[2];
    __shared__ int s_mode;
    __shared__ float s_alpha;

    const int tid  = threadIdx.x;
    const int lane = tid & 31;
    const int warp = tid >> 5;
    const int b    = blockIdx.x / CPB;
    const int rblk = blockIdx.x % CPB;
    const int row0 = rblk * RPC;
    const int rows = min(RPC, MP - row0);   // 28 or 17

    if (tid == 0) {
        s_gen0 = *((volatile unsigned int*)&g_gen);
        s_cnt[0] = 0; s_cnt[1] = 0;
        s_alpha = alphap[0];
        // mask dtype detect: byte bools (all-true window => 0x01010101) vs 4-byte
        const unsigned int* rw = (const unsigned int*)rmaskp;
        int mode = 1;
        #pragma unroll
        for (int k = 0; k < 8; k++)
            if (rw[k] == 0x01010101u) mode = 0;
        s_mode = mode;
    }
    __syncthreads();

    // ---- mask counts ----
    {
        int pr = 0, pc = 0;
        if (s_mode == 1) {
            const unsigned int* rm = (const unsigned int*)rmaskp + b * MDIM;
            const unsigned int* cm = (const unsigned int*)cmaskp + b * MDIM;
            #pragma unroll
            for (int k = 0; k < 4; k++) {
                int i = tid * 4 + k;
                pr += (rm[i] != 0u);
                pc += (cm[i] != 0u);
            }
        } else {
            const unsigned char* rm = (const unsigned char*)rmaskp + b * MDIM;
            const unsigned char* cm = (const unsigned char*)cmaskp + b * MDIM;
            #pragma unroll
            for (int k = 0; k < 4; k++) {
                int i = tid * 4 + k;
                pr += (rm[i] != 0);
                pc += (cm[i] != 0);
            }
        }
        for (int o = 16; o; o >>= 1) {
            pr += __shfl_xor_sync(~0u, pr, o);
            pc += __shfl_xor_sync(~0u, pc, o);
        }
        if (lane == 0) { atomicAdd(&s_cnt[0], pr); atomicAdd(&s_cnt[1], pc); }
    }
    __syncthreads();

    const float R      = (float)s_cnt[0];
    const float C      = (float)s_cnt[1];
    const float norm   = -logf(R + C);
    const float logmuD = logf(C) + norm;
    const float lognuD = logf(R) + norm;
    const float muR    = 1.0f / (R + C);       // exp(norm)
    const float muD    = C / (R + C);          // exp(logmuD)
    const float nuD    = R / (R + C);          // exp(lognuD)
    const float alpha  = s_alpha;
    const float ea     = expf(alpha);

    // ---- build fp32 row slab E[row, :] ----
    const float* sb = scores + (size_t)b * MDIM * MDIM;
    for (int rr = 0; rr < rows; rr++) {
        const int row = row0 + rr;
        float* dst = rowSlab + rr * SF;
        if (row < MDIM) {
            const float* sp = sb + (size_t)row * MDIM;
            for (int j = tid; j < SF; j += TPB)
                dst[j] = (j < MDIM) ? expf(sp[j]) : ((j == MDIM) ? ea : 0.f);
        } else {
            for (int j = tid; j < SF; j += TPB)
                dst[j] = (j < MP) ? ea : 0.f;
        }
    }

    // ---- zero slot 0 share; init w_v = exp(v0) = 1 ----
    if (tid < 28) {
        int id = blockIdx.x * 28 + tid;
        if (id < 4 * SF) (&g_acc[0][0][0])[id] = 0.f;
    }
    for (int j = tid; j < SF; j += TPB) vecbuf[j] = (j < MP) ? 1.f : 0.f;

    unsigned int bar = 0;
    grid_barrier(&bar, s_gen0);   // slot0 zeroed everywhere, w_v ready

    const float4* slab4 = (const float4*)rowSlab;        // 257 float4 per row

    for (int it = 0; it < NITER; it++) {
        // ---- zero slot (it+1)%3 share (2 barriers from any reader/writer) ----
        if (tid < 28) {
            int id = blockIdx.x * 28 + tid;
            if (id < 4 * SF) (&g_acc[(it + 1) % 3][0][0])[id] = 0.f;
        }

        // ========== phase A: rowsum r_i = sum_j E_ij w_v[j]; w_u = mu_i / r_i ========
        float4 wreg[8];
        {
            const float4* v4 = (const float4*)vecbuf;
            #pragma unroll
            for (int i = 0; i < 8; i++) wreg[i] = v4[lane + 32 * i];
        }
        const float wtail = vecbuf[1024];

        for (int rr = warp; rr < rows; rr += 8) {
            const float4* rp = slab4 + rr * 257;
            float a0 = 0.f, a1 = 0.f, a2 = 0.f, a3 = 0.f;
            #pragma unroll
            for (int i = 0; i < 8; i++) {
                const float4 p = rp[lane + 32 * i];
                a0 += p.x * wreg[i].x;
                a1 += p.y * wreg[i].y;
                a2 += p.z * wreg[i].z;
                a3 += p.w * wreg[i].w;
            }
            float acc = (a0 + a1) + (a2 + a3);
            if (lane == 0) acc += rowSlab[rr * SF + 1024] * wtail;
            for (int o = 16; o; o >>= 1) acc += __shfl_xor_sync(~0u, acc, o);
            if (lane == 0) {
                const float mu = (row0 + rr == MDIM) ? muD : muR;
                w_buf[rr] = mu / acc;
                r_buf[rr] = acc;
            }
        }
        __syncthreads();   // w_buf ready

        // ========== phase B: partial colsums over our rows -> RED into slot it%3 =====
        {
            float4 acc4 = make_float4(0.f, 0.f, 0.f, 0.f);
            float  accT = 0.f;
            for (int rr = 0; rr < rows; rr++) {
                const float w  = w_buf[rr];
                const float4 e = slab4[rr * 257 + tid];
                acc4.x += e.x * w; acc4.y += e.y * w;
                acc4.z += e.z * w; acc4.w += e.w * w;
                if (tid == 0) accT += rowSlab[rr * SF + 1024] * w;
            }
            float* dst = &g_acc[it % 3][b][tid * 4];
            atomicAdd(dst + 0, acc4.x);
            atomicAdd(dst + 1, acc4.y);
            atomicAdd(dst + 2, acc4.z);
            atomicAdd(dst + 3, acc4.w);
            if (tid == 0) atomicAdd(&g_acc[it % 3][b][1024], accT);
        }

        grid_barrier(&bar, s_gen0);   // colsums complete everywhere

        // ========== w_v[j] = nu_j / colsum_j (full vector, local) ====================
        if (it < NITER - 1) {
            const float* av = g_acc[it % 3][b];
            for (int j = tid; j < SF; j += TPB) {
                float w = 0.f;
                if (j < MP) {
                    const float sv = __ldcg(&av[j]);
                    const float nu = (j == MDIM) ? nuD : muR;
                    w = nu / sv;
                }
                vecbuf[j] = w;
            }
            __syncthreads();
        }
    }

    // ================= epilogue: out = S + u + v - norm ==============================
    {
        const float* av = g_acc[(NITER - 1) % 3][b];
        for (int j = tid; j < MP; j += TPB) {
            const float sv = __ldcg(&av[j]);
            const float ln = (j == MDIM) ? lognuD : norm;
            vecbuf[j] = ln - logf(sv);        // v_j
        }
    }
    __syncthreads();

    float* ob = out + (size_t)b * MP * MP;
    for (int rr = 0; rr < rows; rr++) {
        const int row = row0 + rr;
        const float lm   = (row == MDIM) ? logmuD : norm;
        const float base = (lm - logf(r_buf[rr])) - norm;   // u_i - norm
        float* op = ob + (size_t)row * MP;
        if (row < MDIM) {
            const float* sp = sb + (size_t)row * MDIM;
            for (int j = tid; j < MP; j += TPB) {
                const float s = (j < MDIM) ? sp[j] : alpha;
                op[j] = s + base + vecbuf[j];
            }
        } else {
            for (int j = tid; j < MP; j += TPB)
                op[j] = alpha + base + vecbuf[j];
        }
    }
}

extern "C" void kernel_launch(void* const* d_in, const int* in_sizes, int n_in,
                              void* d_out, int out_size)
{
    const float* scores = (const float*)d_in[0];
    const void*  rmask  = d_in[1];
    const void*  cmask  = d_in[2];
    const float* alphap = (const float*)d_in[3];
    float*       out    = (float*)d_out;

    cudaFuncSetAttribute(sinkhorn_kernel,
                         cudaFuncAttributeMaxDynamicSharedMemorySize, SMEM_BYTES);
    sinkhorn_kernel<<<NCTA, TPB, SMEM_BYTES>>>(scores, rmask, cmask, alphap, out);
}

// round 5
// speedup vs baseline: 1.5595x; 1.3490x over previous
#include <cuda_runtime.h>
#include <cstdint>

// Persistent-kernel Sinkhorn, ratio form. fp32 slab in SMEM, 148 CTAs (1/SM).
// Batches are fully independent: 37-CTA barrier domains per batch.
// Col sums: 8-way striped RED accumulators (contention <=5) + 8-copy gather.

#define NCTA   148
#define CPB    37
#define RPC    28
#define SF     1028
#define MDIM   1024
#define MP     1025
#define NITER  100
#define TPB    512
#define NCOPY  8

#define SLAB_BYTES (RPC * SF * 4)
#define VEC_OFF    SLAB_BYTES
#define PBUF_OFF   (SLAB_BYTES + SF * 4)
#define WBUF_OFF   (PBUF_OFF + SF * 4)
#define SMEM_BYTES (WBUF_OFF + 64 * 4)

__device__ float        g_acc[3][4][NCOPY][SF];   // rotating striped colsum accumulators
__device__ unsigned int g_cnt[4];                 // per-batch arrival counters
__device__ unsigned int g_gen[4];                 // per-batch generations

__device__ __forceinline__ void batch_barrier(int b, unsigned int* bar_idx, unsigned int gen0)
{
    __syncthreads();
    unsigned int target = gen0 + (++(*bar_idx));
    if (threadIdx.x == 0) {
        unsigned int old;
        asm volatile("atom.acq_rel.gpu.add.u32 %0, [%1], %2;"
                     : "=r"(old) : "l"(&g_cnt[b]), "r"(1u) : "memory");
        if (old % CPB == CPB - 1u) {
            asm volatile("red.release.gpu.add.u32 [%0], %1;"
                         :: "l"(&g_gen[b]), "r"(1u) : "memory");
        } else {
            unsigned int g;
            do {
                asm volatile("ld.acquire.gpu.u32 %0, [%1];"
                             : "=r"(g) : "l"(&g_gen[b]) : "memory");
            } while ((int)(g - target) < 0);
        }
    }
    __syncthreads();
}

__global__ void __launch_bounds__(TPB, 1)
sinkhorn_kernel(const float* __restrict__ scores,
                const void* __restrict__ rmaskp,
                const void* __restrict__ cmaskp,
                const float* __restrict__ alphap,
                float* __restrict__ out)
{
    extern __shared__ unsigned char smem[];
    float* rowSlab = (float*)smem;                   // RPC x SF
    float* vecbuf  = (float*)(smem + VEC_OFF);       // SF: w_v (then v)
    float* pbuf    = (float*)(smem + PBUF_OFF);      // SF: phase-B half-combine
    float* w_buf   = (float*)(smem + WBUF_OFF);      // 28 w_u
    float* r_buf   = w_buf + 32;                     // 28 rowsums

    __shared__ unsigned int s_gen0;
    __shared__ int s_cnt[2];
    __shared__ int s_mode;
    __shared__ float s_alpha;

    const int tid  = threadIdx.x;
    const int lane = tid & 31;
    const int warp = tid >> 5;
    const int b    = blockIdx.x / CPB;
    const int rblk = blockIdx.x % CPB;
    const int row0 = rblk * RPC;
    const int rows = min(RPC, MP - row0);   // 28 or 17
    const int copy = rblk & (NCOPY - 1);

    if (tid == 0) {
        s_gen0 = *((volatile unsigned int*)&g_gen[b]);
        s_cnt[0] = 0; s_cnt[1] = 0;
        s_alpha = alphap[0];
        const unsigned int* rw = (const unsigned int*)rmaskp;
        int mode = 1;                                 // 4-byte bools
        #pragma unroll
        for (int k = 0; k < 8; k++)
            if (rw[k] == 0x01010101u) mode = 0;       // byte bools
        s_mode = mode;
    }
    __syncthreads();

    // ---- mask counts ----
    {
        int pr = 0, pc = 0;
        if (s_mode == 1) {
            const unsigned int* rm = (const unsigned int*)rmaskp + b * MDIM;
            const unsigned int* cm = (const unsigned int*)cmaskp + b * MDIM;
            #pragma unroll
            for (int k = 0; k < 2; k++) {
                int i = tid * 2 + k;
                pr += (rm[i] != 0u);
                pc += (cm[i] != 0u);
            }
        } else {
            const unsigned char* rm = (const unsigned char*)rmaskp + b * MDIM;
            const unsigned char* cm = (const unsigned char*)cmaskp + b * MDIM;
            #pragma unroll
            for (int k = 0; k < 2; k++) {
                int i = tid * 2 + k;
                pr += (rm[i] != 0);
                pc += (cm[i] != 0);
            }
        }
        for (int o = 16; o; o >>= 1) {
            pr += __shfl_xor_sync(~0u, pr, o);
            pc += __shfl_xor_sync(~0u, pc, o);
        }
        if (lane == 0) { atomicAdd(&s_cnt[0], pr); atomicAdd(&s_cnt[1], pc); }
    }
    __syncthreads();

    const float R      = (float)s_cnt[0];
    const float C      = (float)s_cnt[1];
    const float norm   = -logf(R + C);
    const float logmuD = logf(C) + norm;
    const float lognuD = logf(R) + norm;
    const float muR    = 1.0f / (R + C);
    const float muD    = C / (R + C);
    const float nuD    = R / (R + C);
    const float alpha  = s_alpha;
    const float ea     = expf(alpha);

    // ---- build fp32 row slab ----
    const float* sb = scores + (size_t)b * MDIM * MDIM;
    for (int rr = 0; rr < rows; rr++) {
        const int row = row0 + rr;
        float* dst = rowSlab + rr * SF;
        if (row < MDIM) {
            const float* sp = sb + (size_t)row * MDIM;
            for (int j = tid; j < SF; j += TPB)
                dst[j] = (j < MDIM) ? expf(sp[j]) : ((j == MDIM) ? ea : 0.f);
        } else {
            for (int j = tid; j < SF; j += TPB)
                dst[j] = (j < MP) ? ea : 0.f;
        }
    }

    // ---- zero slot 0 (whole array share); init w_v = 1 ----
    {
        float* z = &g_acc[0][0][0][0];
        int id = blockIdx.x * 224 + tid;                       // 224*148 >= 4*8*SF
        if (tid < 224 && id < 4 * NCOPY * SF) z[id] = 0.f;
    }
    for (int j = tid; j < SF; j += TPB) vecbuf[j] = (j < MP) ? 1.f : 0.f;

    unsigned int bar = 0;
    batch_barrier(b, &bar, s_gen0);

    const float4* slab4 = (const float4*)rowSlab;              // 257 float4/row

    for (int it = 0; it < NITER; it++) {
        // ---- zero next slot's share (safe: 1 barrier from writers, 2 from readers) ----
        {
            float* z = &g_acc[(it + 1) % 3][b][0][0];
            int id = rblk * 224 + tid;                         // 224*37 >= 8*SF
            if (tid < 224 && id < NCOPY * SF) z[id] = 0.f;
        }

        // ========== phase A: rowsum; w_u = mu / rowsum ==========
        float4 wreg[8];
        {
            const float4* v4 = (const float4*)vecbuf;
            #pragma unroll
            for (int i = 0; i < 8; i++) wreg[i] = v4[lane + 32 * i];
        }
        const float wtail = vecbuf[1024];

        for (int rr = warp; rr < rows; rr += 16) {
            const float4* rp = slab4 + rr * 257;
            float a0 = 0.f, a1 = 0.f, a2 = 0.f, a3 = 0.f;
            #pragma unroll
            for (int i = 0; i < 8; i++) {
                const float4 p = rp[lane + 32 * i];
                a0 += p.x * wreg[i].x;
                a1 += p.y * wreg[i].y;
                a2 += p.z * wreg[i].z;
                a3 += p.w * wreg[i].w;
            }
            float acc = (a0 + a1) + (a2 + a3);
            if (lane == 0) acc += rowSlab[rr * SF + 1024] * wtail;
            for (int o = 16; o; o >>= 1) acc += __shfl_xor_sync(~0u, acc, o);
            if (lane == 0) {
                const float mu = (row0 + rr == MDIM) ? muD : muR;
                w_buf[rr] = __fdividef(mu, acc);
                r_buf[rr] = acc;
            }
        }
        __syncthreads();

        // ========== phase B: half-split partial colsums -> striped RED ==========
        {
            const int half = tid >> 8;          // 0/1
            const int t    = tid & 255;
            const int rlo  = half * 14;
            const int rhi  = min(rows, rlo + 14);
            float4 acc4 = make_float4(0.f, 0.f, 0.f, 0.f);
            float  accT = 0.f;
            for (int rr = rlo; rr < rhi; rr++) {
                const float w  = w_buf[rr];
                const float4 e = slab4[rr * 257 + t];
                acc4.x += e.x * w; acc4.y += e.y * w;
                acc4.z += e.z * w; acc4.w += e.w * w;
                if (t == 0) accT += rowSlab[rr * SF + 1024] * w;
            }
            if (half == 1) {
                ((float4*)pbuf)[t] = acc4;
                if (t == 0) pbuf[1024] = accT;
            }
            __syncthreads();
            if (half == 0) {
                const float4 o = ((float4*)pbuf)[t];
                acc4.x += o.x; acc4.y += o.y; acc4.z += o.z; acc4.w += o.w;
                float* dst = &g_acc[it % 3][b][copy][t * 4];
                atomicAdd(dst + 0, acc4.x);
                atomicAdd(dst + 1, acc4.y);
                atomicAdd(dst + 2, acc4.z);
                atomicAdd(dst + 3, acc4.w);
                if (t == 0) atomicAdd(&g_acc[it % 3][b][copy][1024], accT + pbuf[1024]);
            }
        }

        batch_barrier(b, &bar, s_gen0);

        // ========== w_v[j] = nu_j / sum over 8 copies ==========
        if (it < NITER - 1) {
            const float (*av)[SF] = g_acc[it % 3][b];
            for (int j = tid; j < SF; j += TPB) {
                float w = 0.f;
                if (j < MP) {
                    float s = 0.f;
                    #pragma unroll
                    for (int c = 0; c < NCOPY; c++) s += __ldcg(&av[c][j]);
                    const float nu = (j == MDIM) ? nuD : muR;
                    w = __fdividef(nu, s);
                }
                vecbuf[j] = w;
            }
            __syncthreads();
        }
    }

    // ================= epilogue: out = S + u + v - norm =================
    {
        const float (*av)[SF] = g_acc[(NITER - 1) % 3][b];
        for (int j = tid; j < MP; j += TPB) {
            float s = 0.f;
            #pragma unroll
            for (int c = 0; c < NCOPY; c++) s += __ldcg(&av[c][j]);
            const float ln = (j == MDIM) ? lognuD : norm;
            vecbuf[j] = ln - logf(s);                   // v_j
        }
    }
    __syncthreads();

    float* ob = out + (size_t)b * MP * MP;
    for (int rr = 0; rr < rows; rr++) {
        const int row = row0 + rr;
        const float lm   = (row == MDIM) ? logmuD : norm;
        const float base = (lm - logf(r_buf[rr])) - norm;   // u_i - norm
        float* op = ob + (size_t)row * MP;
        if (row < MDIM) {
            const float* sp = sb + (size_t)row * MDIM;
            for (int j = tid; j < MP; j += TPB) {
                const float s = (j < MDIM) ? sp[j] : alpha;
                op[j] = s + base + vecbuf[j];
            }
        } else {
            for (int j = tid; j < MP; j += TPB)
                op[j] = alpha + base + vecbuf[j];
        }
    }
}

extern "C" void kernel_launch(void* const* d_in, const int* in_sizes, int n_in,
                              void* d_out, int out_size)
{
    const float* scores = (const float*)d_in[0];
    const void*  rmask  = d_in[1];
    const void*  cmask  = d_in[2];
    const float* alphap = (const float*)d_in[3];
    float*       out    = (float*)d_out;

    cudaFuncSetAttribute(sinkhorn_kernel,
                         cudaFuncAttributeMaxDynamicSharedMemorySize, SMEM_BYTES);
    sinkhorn_kernel<<<NCTA, TPB, SMEM_BYTES>>>(scores, rmask, cmask, alphap, out);
}

// round 6
// speedup vs baseline: 14.5121x; 9.3053x over previous
#include <cuda_runtime.h>
#include <cstdint>

// Persistent-kernel Sinkhorn, ratio form. fp32 slab in SMEM, 148 CTAs (1/SM).
// Batches independent: 37-CTA barrier domains. Col sums: 8-way striped RED +
// 8-copy gather. NEW: early exit when max |exp(v)_new/exp(v)_old - 1| < 2e-5
// (decision computed identically in every CTA of a batch -> no extra sync).

#define NCTA   148
#define CPB    37
#define RPC    28
#define SF     1028
#define MDIM   1024
#define MP     1025
#define NITER  100
#define TPB    512
#define NCOPY  8
#define CONV_TOL 2e-5f

#define SLAB_BYTES (RPC * SF * 4)
#define VEC_OFF    SLAB_BYTES
#define PBUF_OFF   (SLAB_BYTES + SF * 4)
#define WBUF_OFF   (PBUF_OFF + SF * 4)
#define SMEM_BYTES (WBUF_OFF + 64 * 4)

__device__ float        g_acc[3][4][NCOPY][SF];
__device__ unsigned int g_cnt[4];
__device__ unsigned int g_gen[4];

__device__ __forceinline__ void batch_barrier(int b, unsigned int* bar_idx, unsigned int gen0)
{
    __syncthreads();
    unsigned int target = gen0 + (++(*bar_idx));
    if (threadIdx.x == 0) {
        unsigned int old;
        asm volatile("atom.acq_rel.gpu.add.u32 %0, [%1], %2;"
                     : "=r"(old) : "l"(&g_cnt[b]), "r"(1u) : "memory");
        if (old % CPB == CPB - 1u) {
            asm volatile("red.release.gpu.add.u32 [%0], %1;"
                         :: "l"(&g_gen[b]), "r"(1u) : "memory");
        } else {
            unsigned int g;
            do {
                asm volatile("ld.acquire.gpu.u32 %0, [%1];"
                             : "=r"(g) : "l"(&g_gen[b]) : "memory");
            } while ((int)(g - target) < 0);
        }
    }
    __syncthreads();
}

__global__ void __launch_bounds__(TPB, 1)
sinkhorn_kernel(const float* __restrict__ scores,
                const void* __restrict__ rmaskp,
                const void* __restrict__ cmaskp,
                const float* __restrict__ alphap,
                float* __restrict__ out)
{
    extern __shared__ unsigned char smem[];
    float* rowSlab = (float*)smem;                   // RPC x SF
    float* vecbuf  = (float*)(smem + VEC_OFF);       // SF: w_v
    float* pbuf    = (float*)(smem + PBUF_OFF);      // SF: phase-B half-combine
    float* w_buf   = (float*)(smem + WBUF_OFF);      // 28 w_u
    float* r_buf   = w_buf + 32;                     // 28 rowsums

    __shared__ unsigned int s_gen0;
    __shared__ int s_cnt[2];
    __shared__ int s_mode;
    __shared__ int s_flag;                           // convergence flag
    __shared__ float s_alpha;

    const int tid  = threadIdx.x;
    const int lane = tid & 31;
    const int warp = tid >> 5;
    const int b    = blockIdx.x / CPB;
    const int rblk = blockIdx.x % CPB;
    const int row0 = rblk * RPC;
    const int rows = min(RPC, MP - row0);
    const int copy = rblk & (NCOPY - 1);

    if (tid == 0) {
        s_gen0 = *((volatile unsigned int*)&g_gen[b]);
        s_cnt[0] = 0; s_cnt[1] = 0;
        s_alpha = alphap[0];
        const unsigned int* rw = (const unsigned int*)rmaskp;
        int mode = 1;
        #pragma unroll
        for (int k = 0; k < 8; k++)
            if (rw[k] == 0x01010101u) mode = 0;
        s_mode = mode;
    }
    __syncthreads();

    // ---- mask counts ----
    {
        int pr = 0, pc = 0;
        if (s_mode == 1) {
            const unsigned int* rm = (const unsigned int*)rmaskp + b * MDIM;
            const unsigned int* cm = (const unsigned int*)cmaskp + b * MDIM;
            #pragma unroll
            for (int k = 0; k < 2; k++) {
                int i = tid * 2 + k;
                pr += (rm[i] != 0u);
                pc += (cm[i] != 0u);
            }
        } else {
            const unsigned char* rm = (const unsigned char*)rmaskp + b * MDIM;
            const unsigned char* cm = (const unsigned char*)cmaskp + b * MDIM;
            #pragma unroll
            for (int k = 0; k < 2; k++) {
                int i = tid * 2 + k;
                pr += (rm[i] != 0);
                pc += (cm[i] != 0);
            }
        }
        for (int o = 16; o; o >>= 1) {
            pr += __shfl_xor_sync(~0u, pr, o);
            pc += __shfl_xor_sync(~0u, pc, o);
        }
        if (lane == 0) { atomicAdd(&s_cnt[0], pr); atomicAdd(&s_cnt[1], pc); }
    }
    __syncthreads();

    const float R      = (float)s_cnt[0];
    const float C      = (float)s_cnt[1];
    const float norm   = -logf(R + C);
    const float logmuD = logf(C) + norm;
    const float lognuD = logf(R) + norm;
    const float muR    = 1.0f / (R + C);
    const float muD    = C / (R + C);
    const float nuD    = R / (R + C);
    const float alpha  = s_alpha;
    const float ea     = expf(alpha);

    // ---- build fp32 row slab ----
    const float* sb = scores + (size_t)b * MDIM * MDIM;
    for (int rr = 0; rr < rows; rr++) {
        const int row = row0 + rr;
        float* dst = rowSlab + rr * SF;
        if (row < MDIM) {
            const float* sp = sb + (size_t)row * MDIM;
            for (int j = tid; j < SF; j += TPB)
                dst[j] = (j < MDIM) ? expf(sp[j]) : ((j == MDIM) ? ea : 0.f);
        } else {
            for (int j = tid; j < SF; j += TPB)
                dst[j] = (j < MP) ? ea : 0.f;
        }
    }

    // ---- zero slot 0 (whole array share); init w_v = 1 ----
    {
        float* z = &g_acc[0][0][0][0];
        int id = blockIdx.x * 224 + tid;
        if (tid < 224 && id < 4 * NCOPY * SF) z[id] = 0.f;
    }
    for (int j = tid; j < SF; j += TPB) vecbuf[j] = (j < MP) ? 1.f : 0.f;

    unsigned int bar = 0;
    batch_barrier(b, &bar, s_gen0);

    const float4* slab4 = (const float4*)rowSlab;

    int last = NITER - 1;
    for (int it = 0; it < NITER; it++) {
        // ========== phase A: rowsum; w_u = mu / rowsum ==========
        float4 wreg[8];
        {
            const float4* v4 = (const float4*)vecbuf;
            #pragma unroll
            for (int i = 0; i < 8; i++) wreg[i] = v4[lane + 32 * i];
        }
        const float wtail = vecbuf[1024];

        for (int rr = warp; rr < rows; rr += 16) {
            const float4* rp = slab4 + rr * 257;
            float a0 = 0.f, a1 = 0.f, a2 = 0.f, a3 = 0.f;
            #pragma unroll
            for (int i = 0; i < 8; i++) {
                const float4 p = rp[lane + 32 * i];
                a0 += p.x * wreg[i].x;
                a1 += p.y * wreg[i].y;
                a2 += p.z * wreg[i].z;
                a3 += p.w * wreg[i].w;
            }
            float acc = (a0 + a1) + (a2 + a3);
            if (lane == 0) acc += rowSlab[rr * SF + 1024] * wtail;
            for (int o = 16; o; o >>= 1) acc += __shfl_xor_sync(~0u, acc, o);
            if (lane == 0) {
                const float mu = (row0 + rr == MDIM) ? muD : muR;
                w_buf[rr] = __fdividef(mu, acc);
                r_buf[rr] = acc;
            }
        }
        if (tid == 0) s_flag = 1;      // ordered before use by the barrier below
        __syncthreads();

        // ========== phase B: half-split partial colsums -> striped RED ==========
        {
            const int half = tid >> 8;
            const int t    = tid & 255;
            const int rlo  = half * 14;
            const int rhi  = min(rows, rlo + 14);
            float4 acc4 = make_float4(0.f, 0.f, 0.f, 0.f);
            float  accT = 0.f;
            for (int rr = rlo; rr < rhi; rr++) {
                const float w  = w_buf[rr];
                const float4 e = slab4[rr * 257 + t];
                acc4.x += e.x * w; acc4.y += e.y * w;
                acc4.z += e.z * w; acc4.w += e.w * w;
                if (t == 0) accT += rowSlab[rr * SF + 1024] * w;
            }
            if (half == 1) {
                ((float4*)pbuf)[t] = acc4;
                if (t == 0) pbuf[1024] = accT;
            }
            __syncthreads();
            if (half == 0) {
                const float4 o = ((float4*)pbuf)[t];
                acc4.x += o.x; acc4.y += o.y; acc4.z += o.z; acc4.w += o.w;
                float* dst = &g_acc[it % 3][b][copy][t * 4];
                atomicAdd(dst + 0, acc4.x);
                atomicAdd(dst + 1, acc4.y);
                atomicAdd(dst + 2, acc4.z);
                atomicAdd(dst + 3, acc4.w);
                if (t == 0) atomicAdd(&g_acc[it % 3][b][copy][1024], accT + pbuf[1024]);
            }
        }

        // ---- zero next slot's share (overlap with barrier arrival) ----
        {
            float* z = &g_acc[(it + 1) % 3][b][0][0];
            int id = rblk * 224 + tid;
            if (tid < 224 && id < NCOPY * SF) z[id] = 0.f;
        }

        batch_barrier(b, &bar, s_gen0);

        // ========== w_v[j] = nu_j / colsum; convergence test ==========
        if (it < NITER - 1) {
            const float (*av)[SF] = g_acc[it % 3][b];
            int conv = 1;
            for (int j = tid; j < SF; j += TPB) {
                float w = 0.f;
                if (j < MP) {
                    float s = 0.f;
                    #pragma unroll
                    for (int c = 0; c < NCOPY; c++) s += __ldcg(&av[c][j]);
                    const float nu = (j == MDIM) ? nuD : muR;
                    w = __fdividef(nu, s);
                    const float wold = vecbuf[j];
                    if (fabsf(w - wold) > CONV_TOL * wold) conv = 0;
                }
                vecbuf[j] = w;
            }
            if (!conv) s_flag = 0;     // benign race: all writers store 0
            __syncthreads();
            if (s_flag) { last = it; break; }   // identical decision in all CTAs
        }
    }

    // ================= epilogue: out = S + u + v - norm =================
    {
        const float (*av)[SF] = g_acc[last % 3][b];
        for (int j = tid; j < MP; j += TPB) {
            float s = 0.f;
            #pragma unroll
            for (int c = 0; c < NCOPY; c++) s += __ldcg(&av[c][j]);
            const float ln = (j == MDIM) ? lognuD : norm;
            vecbuf[j] = ln - logf(s);
        }
    }
    __syncthreads();

    float* ob = out + (size_t)b * MP * MP;
    for (int rr = 0; rr < rows; rr++) {
        const int row = row0 + rr;
        const float lm   = (row == MDIM) ? logmuD : norm;
        const float base = (lm - logf(r_buf[rr])) - norm;
        float* op = ob + (size_t)row * MP;
        if (row < MDIM) {
            const float* sp = sb + (size_t)row * MDIM;
            for (int j = tid; j < MP; j += TPB) {
                const float s = (j < MDIM) ? sp[j] : alpha;
                op[j] = s + base + vecbuf[j];
            }
        } else {
            for (int j = tid; j < MP; j += TPB)
                op[j] = alpha + base + vecbuf[j];
        }
    }
}

extern "C" void kernel_launch(void* const* d_in, const int* in_sizes, int n_in,
                              void* d_out, int out_size)
{
    const float* scores = (const float*)d_in[0];
    const void*  rmask  = d_in[1];
    const void*  cmask  = d_in[2];
    const float* alphap = (const float*)d_in[3];
    float*       out    = (float*)d_out;

    cudaFuncSetAttribute(sinkhorn_kernel,
                         cudaFuncAttributeMaxDynamicSharedMemorySize, SMEM_BYTES);
    sinkhorn_kernel<<<NCTA, TPB, SMEM_BYTES>>>(scores, rmask, cmask, alphap, out);
}